// round 14
// baseline (speedup 1.0000x reference)
#include <cuda_runtime.h>
#include <cuda_fp16.h>
#include <cstdint>

// CausalSelfAttention: B=4, T=2048, C=1024, H=16, dk=64.
// R14: GEMM re-shaped for 16 warps/SM: 256-thread CTAs (8 warps, 2m x 4n),
// GN=128, warp tile 64x32 (c=64 regs), __launch_bounds__(256,2).
// Attention reverted to R12 form (unconditional rescale; the R13 skip cost).

#define B_   4
#define T_   2048
#define C_   1024
#define H_   16
#define DK_  64
#define M_   (B_ * T_)        // 8192
#define N_QKV (3 * C_)        // 3072

#define QKV_ELEMS ((size_t)B_ * H_ * T_ * DK_)
__device__ __align__(16) __half g_Qhi[QKV_ELEMS];   // scaled by 0.125*log2e
__device__ __align__(16) __half g_Qlo[QKV_ELEMS];
__device__ __align__(16) __half g_K[QKV_ELEMS];     // single fp16
__device__ __align__(16) __half g_V[QKV_ELEMS];     // single fp16
__device__ __align__(16) __half g_Ahi[(size_t)M_ * C_];
__device__ __align__(16) __half g_Alo[(size_t)M_ * C_];
__device__ __align__(16) __half g_Wh[(size_t)(N_QKV + C_ + 128) * C_];

// ---------------------------------------------------------------------------
// helpers
// ---------------------------------------------------------------------------
__device__ __forceinline__ uint32_t smem_u32(const void* p) {
    uint32_t a;
    asm("{ .reg .u64 t; cvta.to.shared.u64 t, %1; cvt.u32.u64 %0, t; }"
        : "=r"(a) : "l"(p));
    return a;
}
__device__ __forceinline__ void cp_async16(uint32_t dst, const void* src) {
    asm volatile("cp.async.ca.shared.global [%0], [%1], 16;"
                 :: "r"(dst), "l"(__cvta_generic_to_global(src)) : "memory");
}
__device__ __forceinline__ void ldsm_x4(uint32_t& r0, uint32_t& r1,
                                        uint32_t& r2, uint32_t& r3, uint32_t a) {
    asm volatile("ldmatrix.sync.aligned.m8n8.x4.shared.b16 {%0,%1,%2,%3}, [%4];"
                 : "=r"(r0), "=r"(r1), "=r"(r2), "=r"(r3) : "r"(a));
}
__device__ __forceinline__ void ldsm_x4t(uint32_t& r0, uint32_t& r1,
                                         uint32_t& r2, uint32_t& r3, uint32_t a) {
    asm volatile("ldmatrix.sync.aligned.m8n8.x4.trans.shared.b16 {%0,%1,%2,%3}, [%4];"
                 : "=r"(r0), "=r"(r1), "=r"(r2), "=r"(r3) : "r"(a));
}
__device__ __forceinline__ void mma_f16(float* c, const uint32_t* a,
                                        uint32_t b0, uint32_t b1) {
    asm volatile(
        "mma.sync.aligned.m16n8k16.row.col.f32.f16.f16.f32 "
        "{%0,%1,%2,%3}, {%4,%5,%6,%7}, {%8,%9}, {%0,%1,%2,%3};"
        : "+f"(c[0]), "+f"(c[1]), "+f"(c[2]), "+f"(c[3])
        : "r"(a[0]), "r"(a[1]), "r"(a[2]), "r"(a[3]), "r"(b0), "r"(b1));
}
__device__ __forceinline__ void split_pack(float x, float y,
                                           uint32_t& hi, uint32_t& lo) {
    __half hx = __float2half_rn(x);
    __half hy = __float2half_rn(y);
    __half2 h; h.x = hx; h.y = hy;
    hi = *(uint32_t*)&h;
    __half2 l;
    l.x = __float2half_rn(x - __half2float(hx));
    l.y = __float2half_rn(y - __half2float(hy));
    lo = *(uint32_t*)&l;
}
__device__ __forceinline__ uint32_t pack_h2(float x, float y) {
    __half2 h; h.x = __float2half_rn(x); h.y = __float2half_rn(y);
    return *(uint32_t*)&h;
}
__device__ __forceinline__ uint32_t ex2_f16x2(float x, float y) {
    uint32_t d;
    asm("{ .reg .b32 t;\n\t"
        "cvt.rn.f16x2.f32 t, %2, %1;\n\t"
        "ex2.approx.f16x2 %0, t; }"
        : "=r"(d) : "f"(x), "f"(y));
    return d;
}
__device__ __forceinline__ float ex2_f32(float x) {
    float d;
    asm("ex2.approx.f32 %0, %1;" : "=f"(d) : "f"(x));
    return d;
}

// ---------------------------------------------------------------------------
// Split fp32 -> fp16 hi/lo (x input only).
// ---------------------------------------------------------------------------
__global__ void __launch_bounds__(256) split_act_kernel(const float* __restrict__ src)
{
    size_t i = ((size_t)blockIdx.x * 256 + threadIdx.x) * 4;
    float4 v = *(const float4*)(src + i);
    __half hx = __float2half_rn(v.x);
    __half hy = __float2half_rn(v.y);
    __half hz = __float2half_rn(v.z);
    __half hw = __float2half_rn(v.w);
    __half h2[4] = { hx, hy, hz, hw };
    *(uint2*)(g_Ahi + i) = *(uint2*)h2;
    __half l2[4] = {
        __float2half_rn(v.x - __half2float(hx)),
        __float2half_rn(v.y - __half2float(hy)),
        __float2half_rn(v.z - __half2float(hz)),
        __float2half_rn(v.w - __half2float(hw)) };
    *(uint2*)(g_Alo + i) = *(uint2*)l2;
}

// ---------------------------------------------------------------------------
// Merged weight transpose: bx < 96 -> W_qkv, else W_proj (offset N_QKV).
// ---------------------------------------------------------------------------
__global__ void __launch_bounds__(256) split_w_kernel(
    const float* __restrict__ Wq, const float* __restrict__ Wp)
{
    __shared__ float tile[32][33];
    const int tx = threadIdx.x, ty = threadIdx.y;
    const int bx = blockIdx.x;
    const bool is_q = bx < (N_QKV / 32);
    const float* W = is_q ? Wq : Wp;
    const int Ncols = is_q ? N_QKV : C_;
    const int row_off = is_q ? 0 : N_QKV;
    const int n0 = (is_q ? bx : bx - N_QKV / 32) * 32;
    const int k0 = blockIdx.y * 32;
    #pragma unroll
    for (int j = ty; j < 32; j += 8)
        tile[j][tx] = W[(size_t)(k0 + j) * Ncols + n0 + tx];
    __syncthreads();
    #pragma unroll
    for (int j = ty; j < 32; j += 8) {
        size_t o = (size_t)(row_off + n0 + j) * C_ + k0 + tx;
        g_Wh[o] = __float2half_rn(tile[tx][j]);
    }
}

// ---------------------------------------------------------------------------
// mma.sync fp16 GEMM (asymmetric 2-term). Tile 128(M) x 128(N) x 32(K).
// 256 threads = 8 warps (2m x 4n), warp tile 64x32 (c = 64 regs).
// 2-stage ring, one barrier per chunk, 2 CTAs/SM -> 16 warps/SM.
// MODE 0 -> Q/K/V scatter epilogue; 1 -> fp32 out (+Nlim guard).
// ---------------------------------------------------------------------------
#define GM 128
#define GN 128
#define KC 32
#define NCHUNK (C_ / KC)
#define A_ST (GM * 80)              // 10240
#define B_ST (GN * 80)              // 10240
#define STAGE (2 * A_ST + B_ST)     // 30720
#define GEMM_SMEM (2 * STAGE)       // 61440

#define QSCALE 0.18033688011112042f  // 0.125 * log2(e)

extern __shared__ char gemm_smem[];

template<int MODE>
__global__ void __launch_bounds__(256, 2) gemm_f16_kernel(
    const __half* __restrict__ gB,
    const float* __restrict__ bias,
    float* __restrict__ Cout,
    int Nlim)
{
    const int tid = threadIdx.x;
    const int lane = tid & 31;
    const int wid = tid >> 5;           // 0..7
    const int wm = wid & 1;             // 2 m-halves of 64
    const int wn = wid >> 1;            // 4 n-quarters of 32
    const int m0 = blockIdx.y * GM;
    const int n0 = blockIdx.x * GN;

    const uint32_t sbase = smem_u32(gemm_smem);

    float c[4][4][4];                   // 64 accumulators
    #pragma unroll
    for (int i = 0; i < 4; i++)
        #pragma unroll
        for (int j = 0; j < 4; j++)
            #pragma unroll
            for (int k = 0; k < 4; k++)
                c[i][j][k] = 0.f;

    auto issue = [&](int ch) {
        const int k0 = ch * KC;
        const uint32_t sb = sbase + (ch & 1) * STAGE;
        #pragma unroll
        for (int i = 0; i < 2; i++) {          // A hi/lo: 512 16B units each
            int idx = i * 256 + tid;
            int row = idx >> 2, cc = idx & 3;
            size_t go = ((size_t)(m0 + row) << 10) + k0 + cc * 8;
            uint32_t dof = row * 80 + cc * 16;
            cp_async16(sb + dof, g_Ahi + go);
            cp_async16(sb + A_ST + dof, g_Alo + go);
        }
        #pragma unroll
        for (int i = 0; i < 2; i++) {          // B: 512 16B units
            int idx = i * 256 + tid;
            int row = idx >> 2, cc = idx & 3;
            size_t go = ((size_t)(n0 + row) << 10) + k0 + cc * 8;
            uint32_t dof = row * 80 + cc * 16;
            cp_async16(sb + 2 * A_ST + dof, gB + go);
        }
        asm volatile("cp.async.commit_group;" ::: "memory");
    };

    issue(0);

    const uint32_t a_lrow = (lane & 15);
    const uint32_t a_lk   = (lane >> 4) * 16;
    const uint32_t b_lrow = (lane & 7) | ((lane >> 1) & 8);
    const uint32_t b_lk   = ((lane >> 3) & 1) * 16;

    for (int ch = 0; ch < NCHUNK; ch++) {
        asm volatile("cp.async.wait_group 0;" ::: "memory");
        __syncthreads();
        if (ch + 1 < NCHUNK) issue(ch + 1);

        const uint32_t sA = sbase + (ch & 1) * STAGE;
        const uint32_t sB = sA + 2 * A_ST;

        #pragma unroll
        for (int ks = 0; ks < 2; ks++) {
            const uint32_t kb = ks * 32;
            uint32_t ahi[4][4], bb[2][4];
            #pragma unroll
            for (int mf = 0; mf < 4; mf++) {
                uint32_t ad = sA + (wm * 64 + mf * 16 + a_lrow) * 80 + kb + a_lk;
                ldsm_x4(ahi[mf][0], ahi[mf][1], ahi[mf][2], ahi[mf][3], ad);
            }
            #pragma unroll
            for (int np = 0; np < 2; np++) {
                uint32_t bd = sB + (wn * 32 + np * 16 + b_lrow) * 80 + kb + b_lk;
                ldsm_x4(bb[np][0], bb[np][1], bb[np][2], bb[np][3], bd);
            }
            #pragma unroll
            for (int mf = 0; mf < 4; mf++)
                #pragma unroll
                for (int np = 0; np < 2; np++) {
                    mma_f16(c[mf][2 * np],     ahi[mf], bb[np][0], bb[np][1]);
                    mma_f16(c[mf][2 * np + 1], ahi[mf], bb[np][2], bb[np][3]);
                }
            #pragma unroll
            for (int mf = 0; mf < 4; mf++) {
                uint32_t alo[4];
                uint32_t ad = sA + A_ST + (wm * 64 + mf * 16 + a_lrow) * 80 + kb + a_lk;
                ldsm_x4(alo[0], alo[1], alo[2], alo[3], ad);
                #pragma unroll
                for (int np = 0; np < 2; np++) {
                    mma_f16(c[mf][2 * np],     alo, bb[np][0], bb[np][1]);
                    mma_f16(c[mf][2 * np + 1], alo, bb[np][2], bb[np][3]);
                }
            }
        }
    }

    // ---- epilogue ----
    #pragma unroll
    for (int mf = 0; mf < 4; mf++) {
        const int mrow = m0 + wm * 64 + mf * 16 + (lane >> 2);
        #pragma unroll
        for (int nf = 0; nf < 4; nf++) {
            const int n = n0 + wn * 32 + nf * 8 + (lane & 3) * 2;
            if (MODE == 0) {
                const float bx = bias[n], by = bias[n + 1];
                const int which = n >> 10;                 // 0=Q,1=K,2=V
                const int h = (n >> 6) & 15;
                const int d = n & 63;
                const int b = mrow >> 11, t = mrow & (T_ - 1);
                size_t base = (((size_t)(b * H_ + h) * T_ + t) << 6) + d;
                float v0 = c[mf][nf][0] + bx, v1 = c[mf][nf][1] + by;
                float v2 = c[mf][nf][2] + bx, v3 = c[mf][nf][3] + by;
                if (which == 0) {
                    uint32_t hi, lo;
                    split_pack(v0 * QSCALE, v1 * QSCALE, hi, lo);
                    *(uint32_t*)(g_Qhi + base) = hi;
                    *(uint32_t*)(g_Qlo + base) = lo;
                    split_pack(v2 * QSCALE, v3 * QSCALE, hi, lo);
                    *(uint32_t*)(g_Qhi + base + 512) = hi;   // (t+8) << 6
                    *(uint32_t*)(g_Qlo + base + 512) = lo;
                } else {
                    __half* dst = (which == 1) ? g_K : g_V;
                    *(uint32_t*)(dst + base)       = pack_h2(v0, v1);
                    *(uint32_t*)(dst + base + 512) = pack_h2(v2, v3);
                }
            } else if (n < Nlim) {
                const float bx = bias[n], by = bias[n + 1];
                float* p = Cout + (size_t)mrow * C_ + n;
                p[0] = c[mf][nf][0] + bx;
                p[1] = c[mf][nf][1] + by;
                p += (size_t)8 * C_;
                p[0] = c[mf][nf][2] + bx;
                p[1] = c[mf][nf][3] + by;
            }
        }
    }
}

// ---------------------------------------------------------------------------
// MMA flash attention (fp16), log2-domain softmax, ex2.f16x2 P, ones-MMA l.
// 64 q-rows per CTA, 128 threads (4 warps), 3 CTAs/SM, 3-stage K/V ring.
// (R12 form: unconditional rescale.)
// ---------------------------------------------------------------------------
#define ROWB 144
#define ATT_ARR (64 * ROWB)          // 9216
#define ATT_STAGE (2 * ATT_ARR)      // 18432 (K + V)
#define ATT_SMEM (3 * ATT_STAGE)     // 55296
#define ONES2 0x3C003C00u            // fp16x2 {1.0, 1.0}

extern __shared__ char att_smem[];

__global__ void __launch_bounds__(128, 3) attn_mma_kernel()
{
    const uint32_t sb = smem_u32(att_smem);
    const int tid = threadIdx.x, lane = tid & 31, wid = tid >> 5;   // 4 warps
    const int bh = blockIdx.y;
    const int qt = (int)(gridDim.x - 1) - (int)blockIdx.x;   // heavy-first
    const int qb = qt * 64;
    const int ntiles = qt + 1;

    const size_t bhoff = (size_t)bh * T_ * DK_;
    const __half* Kg = g_K + bhoff;
    const __half* Vg = g_V + bhoff;

    {
        const __half* Qh = g_Qhi + bhoff + (size_t)qb * DK_;
        const __half* Ql = g_Qlo + bhoff + (size_t)qb * DK_;
        #pragma unroll
        for (int i = 0; i < 4; i++) {
            int idx = i * 128 + tid;          // 0..511
            int row = idx >> 3, ch = idx & 7;
            cp_async16(sb + row * ROWB + ch * 16, Qh + row * 64 + ch * 8);
            cp_async16(sb + 64 * ROWB + row * ROWB + ch * 16, Ql + row * 64 + ch * 8);
        }
        asm volatile("cp.async.commit_group;" ::: "memory");
        asm volatile("cp.async.wait_group 0;" ::: "memory");
        __syncthreads();
    }
    uint32_t qhi[4][4], qlo[4][4];
    {
        const uint32_t ar = wid * 16 + (lane & 15);          // 0..63
        const uint32_t ac = (lane >> 4) * 16;
        #pragma unroll
        for (int j = 0; j < 4; j++) {
            ldsm_x4(qhi[j][0], qhi[j][1], qhi[j][2], qhi[j][3],
                    sb + ar * ROWB + j * 32 + ac);
            ldsm_x4(qlo[j][0], qlo[j][1], qlo[j][2], qlo[j][3],
                    sb + 64 * ROWB + ar * ROWB + j * 32 + ac);
        }
    }
    __syncthreads();

    auto issue_tile = [&](int kt, int st) {
        const size_t goff = (size_t)kt * 64 * 64;
        const uint32_t s0 = sb + st * ATT_STAGE;
        #pragma unroll
        for (int i = 0; i < 4; i++) {
            int idx = i * 128 + tid;           // 0..511
            int row = idx >> 3, ch = idx & 7;
            cp_async16(s0 + row * ROWB + ch * 16, Kg + goff + row * 64 + ch * 8);
            cp_async16(s0 + ATT_ARR + row * ROWB + ch * 16,
                       Vg + goff + row * 64 + ch * 8);
        }
        asm volatile("cp.async.commit_group;" ::: "memory");
    };

    float O[8][4];
    #pragma unroll
    for (int f = 0; f < 8; f++)
        #pragma unroll
        for (int j = 0; j < 4; j++)
            O[f][j] = 0.f;
    float Ol[4] = { 0.f, 0.f, 0.f, 0.f };
    float m0v = -1e30f, m1v = -1e30f;

    issue_tile(0, 0);
    if (ntiles > 1) issue_tile(1, 1);

    const uint32_t b_lrow = (lane & 7) | ((lane >> 1) & 8);
    const uint32_t b_lk   = ((lane >> 3) & 1) * 16;
    const uint32_t v_row  = lane & 15;
    const uint32_t v_cb   = (lane >> 4) * 16;
    const int q0 = qb + wid * 16 + (lane >> 2);
    const int q1 = q0 + 8;

    for (int kt = 0; kt < ntiles; kt++) {
        if (kt + 1 < ntiles)
            asm volatile("cp.async.wait_group 1;" ::: "memory");
        else
            asm volatile("cp.async.wait_group 0;" ::: "memory");
        __syncthreads();
        if (kt + 2 < ntiles) issue_tile(kt + 2, (kt + 2) % 3);

        const uint32_t sK = sb + (kt % 3) * ATT_STAGE;
        const uint32_t sV = sK + ATT_ARR;

        float c[8][4];
        #pragma unroll
        for (int f = 0; f < 8; f++)
            #pragma unroll
            for (int j = 0; j < 4; j++)
                c[f][j] = 0.f;

        #pragma unroll
        for (int j = 0; j < 4; j++) {
            #pragma unroll
            for (int nb = 0; nb < 4; nb++) {
                uint32_t b0, b1, b2, b3;
                ldsm_x4(b0, b1, b2, b3,
                        sK + (nb * 16 + b_lrow) * ROWB + j * 32 + b_lk);
                mma_f16(c[2 * nb],     qhi[j], b0, b1);
                mma_f16(c[2 * nb + 1], qhi[j], b2, b3);
                mma_f16(c[2 * nb],     qlo[j], b0, b1);
                mma_f16(c[2 * nb + 1], qlo[j], b2, b3);
            }
        }

        if (kt == qt) {
            const int kb = kt * 64;
            #pragma unroll
            for (int f = 0; f < 8; f++) {
                const int kc = kb + f * 8 + (lane & 3) * 2;
                if (kc     > q0) c[f][0] = -1e30f;
                if (kc + 1 > q0) c[f][1] = -1e30f;
                if (kc     > q1) c[f][2] = -1e30f;
                if (kc + 1 > q1) c[f][3] = -1e30f;
            }
        }

        float tm0 = -1e30f, tm1 = -1e30f;
        #pragma unroll
        for (int f = 0; f < 8; f++) {
            tm0 = fmaxf(tm0, fmaxf(c[f][0], c[f][1]));
            tm1 = fmaxf(tm1, fmaxf(c[f][2], c[f][3]));
        }
        tm0 = fmaxf(tm0, __shfl_xor_sync(0xffffffffu, tm0, 1));
        tm0 = fmaxf(tm0, __shfl_xor_sync(0xffffffffu, tm0, 2));
        tm1 = fmaxf(tm1, __shfl_xor_sync(0xffffffffu, tm1, 1));
        tm1 = fmaxf(tm1, __shfl_xor_sync(0xffffffffu, tm1, 2));
        const float mn0 = fmaxf(m0v, tm0), mn1 = fmaxf(m1v, tm1);
        const float cor0 = ex2_f32(m0v - mn0), cor1 = ex2_f32(m1v - mn1);
        m0v = mn0; m1v = mn1;

        #pragma unroll
        for (int f = 0; f < 8; f++) {
            O[f][0] *= cor0; O[f][1] *= cor0;
            O[f][2] *= cor1; O[f][3] *= cor1;
        }
        Ol[0] *= cor0; Ol[1] *= cor0;
        Ol[2] *= cor1; Ol[3] *= cor1;

        uint32_t ph[4][4];
        #pragma unroll
        for (int j = 0; j < 4; j++) {
            ph[j][0] = ex2_f16x2(c[2 * j][0]     - mn0, c[2 * j][1]     - mn0);
            ph[j][1] = ex2_f16x2(c[2 * j][2]     - mn1, c[2 * j][3]     - mn1);
            ph[j][2] = ex2_f16x2(c[2 * j + 1][0] - mn0, c[2 * j + 1][1] - mn0);
            ph[j][3] = ex2_f16x2(c[2 * j + 1][2] - mn1, c[2 * j + 1][3] - mn1);
        }

        #pragma unroll
        for (int j = 0; j < 4; j++) {
            mma_f16(Ol, ph[j], ONES2, ONES2);
            #pragma unroll
            for (int db = 0; db < 4; db++) {
                uint32_t b0, b1, b2, b3;
                ldsm_x4t(b0, b1, b2, b3,
                         sV + (j * 16 + v_row) * ROWB + db * 32 + v_cb);
                mma_f16(O[2 * db],     ph[j], b0, b1);
                mma_f16(O[2 * db + 1], ph[j], b2, b3);
            }
        }
    }

    const float inv0 = 1.f / Ol[0], inv1 = 1.f / Ol[2];
    const int b = bh >> 4, h = bh & 15;
    const int t0 = qb + wid * 16 + (lane >> 2);
    const size_t r0 = ((size_t)b * T_ + t0) * C_ + h * 64;
    const size_t r1 = r0 + (size_t)8 * C_;
    #pragma unroll
    for (int f = 0; f < 8; f++) {
        const int d = f * 8 + (lane & 3) * 2;
        uint32_t hi, lo;
        split_pack(O[f][0] * inv0, O[f][1] * inv0, hi, lo);
        *(uint32_t*)(g_Ahi + r0 + d) = hi;
        *(uint32_t*)(g_Alo + r0 + d) = lo;
        split_pack(O[f][2] * inv1, O[f][3] * inv1, hi, lo);
        *(uint32_t*)(g_Ahi + r1 + d) = hi;
        *(uint32_t*)(g_Alo + r1 + d) = lo;
    }
}

// ---------------------------------------------------------------------------
extern "C" void kernel_launch(void* const* d_in, const int* in_sizes, int n_in,
                              void* d_out, int out_size)
{
    const float* x      = (const float*)d_in[0];
    const float* W_qkv  = (const float*)d_in[1];
    const float* b_qkv  = (const float*)d_in[2];
    const float* W_proj = (const float*)d_in[3];
    const float* b_proj = (const float*)d_in[4];
    float* out = (float*)d_out;

    static int inited = 0;
    if (!inited) {
        cudaFuncSetAttribute(gemm_f16_kernel<0>,
                             cudaFuncAttributeMaxDynamicSharedMemorySize, GEMM_SMEM);
        cudaFuncSetAttribute(gemm_f16_kernel<1>,
                             cudaFuncAttributeMaxDynamicSharedMemorySize, GEMM_SMEM);
        cudaFuncSetAttribute(attn_mma_kernel,
                             cudaFuncAttributeMaxDynamicSharedMemorySize, ATT_SMEM);
        inited = 1;
    }

    __half* Wh_d;
    cudaGetSymbolAddress((void**)&Wh_d, g_Wh);

    dim3 tb(32, 8);
    split_w_kernel<<<dim3(128, C_ / 32), tb>>>(W_qkv, W_proj);
    split_act_kernel<<<(M_ * C_) / (256 * 4), 256>>>(x);

    // qkv: 3072/128 = 24 x 64 = 1536 CTAs, 256 threads, 2 CTAs/SM
    gemm_f16_kernel<0><<<dim3(N_QKV / GN, M_ / GM), 256, GEMM_SMEM>>>(
        Wh_d, b_qkv, nullptr, N_QKV);

    attn_mma_kernel<<<dim3(T_ / 64, B_ * H_), 128, ATT_SMEM>>>();

    // proj: 1024/128 = 8 x 64 = 512 CTAs (exact, no ragged tile)
    gemm_f16_kernel<1><<<dim3(C_ / GN, M_ / GM), 256, GEMM_SMEM>>>(
        Wh_d + (size_t)N_QKV * C_, b_proj, out, C_);
}

// round 15
// speedup vs baseline: 1.1749x; 1.1749x over previous
#include <cuda_runtime.h>
#include <cuda_fp16.h>
#include <cstdint>

// CausalSelfAttention: B=4, T=2048, C=1024, H=16, dk=64.
// R15: GEMM back to the measured-best R10 shape (128 thr, GN=96, 3 CTAs/SM).
// New: qkv A-lo pass (and its staging) skipped for pure-K/V tiles — K/V are
// stored as single fp16 (2^-11) anyway, so the 2^-12 lo-term is below their
// storage rounding. 33% fewer qkv MMAs. Proj keeps both terms.

#define B_   4
#define T_   2048
#define C_   1024
#define H_   16
#define DK_  64
#define M_   (B_ * T_)        // 8192
#define N_QKV (3 * C_)        // 3072

#define QKV_ELEMS ((size_t)B_ * H_ * T_ * DK_)
__device__ __align__(16) __half g_Qhi[QKV_ELEMS];   // scaled by 0.125*log2e
__device__ __align__(16) __half g_Qlo[QKV_ELEMS];
__device__ __align__(16) __half g_K[QKV_ELEMS];     // single fp16
__device__ __align__(16) __half g_V[QKV_ELEMS];     // single fp16
__device__ __align__(16) __half g_Ahi[(size_t)M_ * C_];
__device__ __align__(16) __half g_Alo[(size_t)M_ * C_];
__device__ __align__(16) __half g_Wh[(size_t)(N_QKV + C_ + 128) * C_];

// ---------------------------------------------------------------------------
// helpers
// ---------------------------------------------------------------------------
__device__ __forceinline__ uint32_t smem_u32(const void* p) {
    uint32_t a;
    asm("{ .reg .u64 t; cvta.to.shared.u64 t, %1; cvt.u32.u64 %0, t; }"
        : "=r"(a) : "l"(p));
    return a;
}
__device__ __forceinline__ void cp_async16(uint32_t dst, const void* src) {
    asm volatile("cp.async.ca.shared.global [%0], [%1], 16;"
                 :: "r"(dst), "l"(__cvta_generic_to_global(src)) : "memory");
}
__device__ __forceinline__ void ldsm_x4(uint32_t& r0, uint32_t& r1,
                                        uint32_t& r2, uint32_t& r3, uint32_t a) {
    asm volatile("ldmatrix.sync.aligned.m8n8.x4.shared.b16 {%0,%1,%2,%3}, [%4];"
                 : "=r"(r0), "=r"(r1), "=r"(r2), "=r"(r3) : "r"(a));
}
__device__ __forceinline__ void ldsm_x4t(uint32_t& r0, uint32_t& r1,
                                         uint32_t& r2, uint32_t& r3, uint32_t a) {
    asm volatile("ldmatrix.sync.aligned.m8n8.x4.trans.shared.b16 {%0,%1,%2,%3}, [%4];"
                 : "=r"(r0), "=r"(r1), "=r"(r2), "=r"(r3) : "r"(a));
}
__device__ __forceinline__ void mma_f16(float* c, const uint32_t* a,
                                        uint32_t b0, uint32_t b1) {
    asm volatile(
        "mma.sync.aligned.m16n8k16.row.col.f32.f16.f16.f32 "
        "{%0,%1,%2,%3}, {%4,%5,%6,%7}, {%8,%9}, {%0,%1,%2,%3};"
        : "+f"(c[0]), "+f"(c[1]), "+f"(c[2]), "+f"(c[3])
        : "r"(a[0]), "r"(a[1]), "r"(a[2]), "r"(a[3]), "r"(b0), "r"(b1));
}
__device__ __forceinline__ void split_pack(float x, float y,
                                           uint32_t& hi, uint32_t& lo) {
    __half hx = __float2half_rn(x);
    __half hy = __float2half_rn(y);
    __half2 h; h.x = hx; h.y = hy;
    hi = *(uint32_t*)&h;
    __half2 l;
    l.x = __float2half_rn(x - __half2float(hx));
    l.y = __float2half_rn(y - __half2float(hy));
    lo = *(uint32_t*)&l;
}
__device__ __forceinline__ uint32_t pack_h2(float x, float y) {
    __half2 h; h.x = __float2half_rn(x); h.y = __float2half_rn(y);
    return *(uint32_t*)&h;
}
__device__ __forceinline__ uint32_t ex2_f16x2(float x, float y) {
    uint32_t d;
    asm("{ .reg .b32 t;\n\t"
        "cvt.rn.f16x2.f32 t, %2, %1;\n\t"
        "ex2.approx.f16x2 %0, t; }"
        : "=r"(d) : "f"(x), "f"(y));
    return d;
}
__device__ __forceinline__ float ex2_f32(float x) {
    float d;
    asm("ex2.approx.f32 %0, %1;" : "=f"(d) : "f"(x));
    return d;
}

// ---------------------------------------------------------------------------
// Split fp32 -> fp16 hi/lo (x input only).
// ---------------------------------------------------------------------------
__global__ void __launch_bounds__(256) split_act_kernel(const float* __restrict__ src)
{
    size_t i = ((size_t)blockIdx.x * 256 + threadIdx.x) * 4;
    float4 v = *(const float4*)(src + i);
    __half hx = __float2half_rn(v.x);
    __half hy = __float2half_rn(v.y);
    __half hz = __float2half_rn(v.z);
    __half hw = __float2half_rn(v.w);
    __half h2[4] = { hx, hy, hz, hw };
    *(uint2*)(g_Ahi + i) = *(uint2*)h2;
    __half l2[4] = {
        __float2half_rn(v.x - __half2float(hx)),
        __float2half_rn(v.y - __half2float(hy)),
        __float2half_rn(v.z - __half2float(hz)),
        __float2half_rn(v.w - __half2float(hw)) };
    *(uint2*)(g_Alo + i) = *(uint2*)l2;
}

// ---------------------------------------------------------------------------
// Merged weight transpose: bx < 96 -> W_qkv, else W_proj (offset N_QKV).
// ---------------------------------------------------------------------------
__global__ void __launch_bounds__(256) split_w_kernel(
    const float* __restrict__ Wq, const float* __restrict__ Wp)
{
    __shared__ float tile[32][33];
    const int tx = threadIdx.x, ty = threadIdx.y;
    const int bx = blockIdx.x;
    const bool is_q = bx < (N_QKV / 32);
    const float* W = is_q ? Wq : Wp;
    const int Ncols = is_q ? N_QKV : C_;
    const int row_off = is_q ? 0 : N_QKV;
    const int n0 = (is_q ? bx : bx - N_QKV / 32) * 32;
    const int k0 = blockIdx.y * 32;
    #pragma unroll
    for (int j = ty; j < 32; j += 8)
        tile[j][tx] = W[(size_t)(k0 + j) * Ncols + n0 + tx];
    __syncthreads();
    #pragma unroll
    for (int j = ty; j < 32; j += 8) {
        size_t o = (size_t)(row_off + n0 + j) * C_ + k0 + tx;
        g_Wh[o] = __float2half_rn(tile[tx][j]);
    }
}

// ---------------------------------------------------------------------------
// mma.sync fp16 GEMM (asymmetric 2-term). Tile 128x96x32, 4 warps (2m x 2n),
// warp tile 64x48. 2-stage ring, one barrier per chunk, 3 CTAs/SM.
// MODE 0: Q/K/V scatter epilogue; A-lo pass only when the tile contains Q
//         columns (n0 < C_) — K/V are fp16-rounded anyway.
// MODE 1: fp32 out (+Nlim guard), always 2-term.
// ---------------------------------------------------------------------------
#define GM 128
#define GN 96
#define KC 32
#define NCHUNK (C_ / KC)
#define A_ST (GM * 80)              // 10240
#define B_ST (GN * 80)              // 7680
#define STAGE (2 * A_ST + B_ST)     // 28160
#define GEMM_SMEM (2 * STAGE)       // 56320

#define QSCALE 0.18033688011112042f  // 0.125 * log2(e)

extern __shared__ char gemm_smem[];

template<int MODE>
__global__ void __launch_bounds__(128, 3) gemm_f16_kernel(
    const __half* __restrict__ gB,
    const float* __restrict__ bias,
    float* __restrict__ Cout,
    int Nlim)
{
    const int tid = threadIdx.x;
    const int lane = tid & 31;
    const int wid = tid >> 5;
    const int wm = wid & 1;
    const int wn = wid >> 1;
    const int m0 = blockIdx.y * GM;
    const int n0 = blockIdx.x * GN;

    // A-lo needed only when this tile produces Q (or proj mode, always).
    const bool do_lo = (MODE == 1) || (n0 < C_);

    const uint32_t sbase = smem_u32(gemm_smem);

    float c[4][6][4];
    #pragma unroll
    for (int i = 0; i < 4; i++)
        #pragma unroll
        for (int j = 0; j < 6; j++)
            #pragma unroll
            for (int k = 0; k < 4; k++)
                c[i][j][k] = 0.f;

    auto issue = [&](int ch) {
        const int k0 = ch * KC;
        const uint32_t sb = sbase + (ch & 1) * STAGE;
        #pragma unroll
        for (int i = 0; i < 4; i++) {          // A hi (+ lo when needed)
            int idx = i * 128 + tid;
            int row = idx >> 2, cc = idx & 3;
            size_t go = ((size_t)(m0 + row) << 10) + k0 + cc * 8;
            uint32_t dof = row * 80 + cc * 16;
            cp_async16(sb + dof, g_Ahi + go);
            if (do_lo)
                cp_async16(sb + A_ST + dof, g_Alo + go);
        }
        #pragma unroll
        for (int i = 0; i < 3; i++) {          // B single fp16
            int idx = i * 128 + tid;
            int row = idx >> 2, cc = idx & 3;
            size_t go = ((size_t)(n0 + row) << 10) + k0 + cc * 8;
            uint32_t dof = row * 80 + cc * 16;
            cp_async16(sb + 2 * A_ST + dof, gB + go);
        }
        asm volatile("cp.async.commit_group;" ::: "memory");
    };

    issue(0);

    const uint32_t a_lrow = (lane & 15);
    const uint32_t a_lk   = (lane >> 4) * 16;
    const uint32_t b_lrow = (lane & 7) | ((lane >> 1) & 8);
    const uint32_t b_lk   = ((lane >> 3) & 1) * 16;

    for (int ch = 0; ch < NCHUNK; ch++) {
        asm volatile("cp.async.wait_group 0;" ::: "memory");
        __syncthreads();
        if (ch + 1 < NCHUNK) issue(ch + 1);

        const uint32_t sA = sbase + (ch & 1) * STAGE;
        const uint32_t sB = sA + 2 * A_ST;

        #pragma unroll
        for (int ks = 0; ks < 2; ks++) {
            const uint32_t kb = ks * 32;
            uint32_t ahi[4][4], bb[3][4];
            #pragma unroll
            for (int mf = 0; mf < 4; mf++) {
                uint32_t ad = sA + (wm * 64 + mf * 16 + a_lrow) * 80 + kb + a_lk;
                ldsm_x4(ahi[mf][0], ahi[mf][1], ahi[mf][2], ahi[mf][3], ad);
            }
            #pragma unroll
            for (int np = 0; np < 3; np++) {
                uint32_t bd = sB + (wn * 48 + np * 16 + b_lrow) * 80 + kb + b_lk;
                ldsm_x4(bb[np][0], bb[np][1], bb[np][2], bb[np][3], bd);
            }
            #pragma unroll
            for (int mf = 0; mf < 4; mf++)
                #pragma unroll
                for (int np = 0; np < 3; np++) {
                    mma_f16(c[mf][2 * np],     ahi[mf], bb[np][0], bb[np][1]);
                    mma_f16(c[mf][2 * np + 1], ahi[mf], bb[np][2], bb[np][3]);
                }
            if (do_lo) {
                #pragma unroll
                for (int mf = 0; mf < 4; mf++) {
                    uint32_t alo[4];
                    uint32_t ad = sA + A_ST + (wm * 64 + mf * 16 + a_lrow) * 80 + kb + a_lk;
                    ldsm_x4(alo[0], alo[1], alo[2], alo[3], ad);
                    #pragma unroll
                    for (int np = 0; np < 3; np++) {
                        mma_f16(c[mf][2 * np],     alo, bb[np][0], bb[np][1]);
                        mma_f16(c[mf][2 * np + 1], alo, bb[np][2], bb[np][3]);
                    }
                }
            }
        }
    }

    // ---- epilogue ----
    #pragma unroll
    for (int mf = 0; mf < 4; mf++) {
        const int mrow = m0 + wm * 64 + mf * 16 + (lane >> 2);
        #pragma unroll
        for (int nf = 0; nf < 6; nf++) {
            const int n = n0 + wn * 48 + nf * 8 + (lane & 3) * 2;
            if (MODE == 0) {
                const float bx = bias[n], by = bias[n + 1];
                const int which = n >> 10;                 // 0=Q,1=K,2=V
                const int h = (n >> 6) & 15;
                const int d = n & 63;
                const int b = mrow >> 11, t = mrow & (T_ - 1);
                size_t base = (((size_t)(b * H_ + h) * T_ + t) << 6) + d;
                float v0 = c[mf][nf][0] + bx, v1 = c[mf][nf][1] + by;
                float v2 = c[mf][nf][2] + bx, v3 = c[mf][nf][3] + by;
                if (which == 0) {
                    uint32_t hi, lo;
                    split_pack(v0 * QSCALE, v1 * QSCALE, hi, lo);
                    *(uint32_t*)(g_Qhi + base) = hi;
                    *(uint32_t*)(g_Qlo + base) = lo;
                    split_pack(v2 * QSCALE, v3 * QSCALE, hi, lo);
                    *(uint32_t*)(g_Qhi + base + 512) = hi;   // (t+8) << 6
                    *(uint32_t*)(g_Qlo + base + 512) = lo;
                } else {
                    __half* dst = (which == 1) ? g_K : g_V;
                    *(uint32_t*)(dst + base)       = pack_h2(v0, v1);
                    *(uint32_t*)(dst + base + 512) = pack_h2(v2, v3);
                }
            } else if (n < Nlim) {
                const float bx = bias[n], by = bias[n + 1];
                float* p = Cout + (size_t)mrow * C_ + n;
                p[0] = c[mf][nf][0] + bx;
                p[1] = c[mf][nf][1] + by;
                p += (size_t)8 * C_;
                p[0] = c[mf][nf][2] + bx;
                p[1] = c[mf][nf][3] + by;
            }
        }
    }
}

// ---------------------------------------------------------------------------
// MMA flash attention (fp16), log2-domain softmax, ex2.f16x2 P, ones-MMA l.
// 64 q-rows per CTA, 128 threads (4 warps), 3 CTAs/SM, 3-stage K/V ring.
// (Unconditional rescale — R13's skip measured as a cost.)
// ---------------------------------------------------------------------------
#define ROWB 144
#define ATT_ARR (64 * ROWB)          // 9216
#define ATT_STAGE (2 * ATT_ARR)      // 18432 (K + V)
#define ATT_SMEM (3 * ATT_STAGE)     // 55296
#define ONES2 0x3C003C00u            // fp16x2 {1.0, 1.0}

extern __shared__ char att_smem[];

__global__ void __launch_bounds__(128, 3) attn_mma_kernel()
{
    const uint32_t sb = smem_u32(att_smem);
    const int tid = threadIdx.x, lane = tid & 31, wid = tid >> 5;   // 4 warps
    const int bh = blockIdx.y;
    const int qt = (int)(gridDim.x - 1) - (int)blockIdx.x;   // heavy-first
    const int qb = qt * 64;
    const int ntiles = qt + 1;

    const size_t bhoff = (size_t)bh * T_ * DK_;
    const __half* Kg = g_K + bhoff;
    const __half* Vg = g_V + bhoff;

    {
        const __half* Qh = g_Qhi + bhoff + (size_t)qb * DK_;
        const __half* Ql = g_Qlo + bhoff + (size_t)qb * DK_;
        #pragma unroll
        for (int i = 0; i < 4; i++) {
            int idx = i * 128 + tid;          // 0..511
            int row = idx >> 3, ch = idx & 7;
            cp_async16(sb + row * ROWB + ch * 16, Qh + row * 64 + ch * 8);
            cp_async16(sb + 64 * ROWB + row * ROWB + ch * 16, Ql + row * 64 + ch * 8);
        }
        asm volatile("cp.async.commit_group;" ::: "memory");
        asm volatile("cp.async.wait_group 0;" ::: "memory");
        __syncthreads();
    }
    uint32_t qhi[4][4], qlo[4][4];
    {
        const uint32_t ar = wid * 16 + (lane & 15);          // 0..63
        const uint32_t ac = (lane >> 4) * 16;
        #pragma unroll
        for (int j = 0; j < 4; j++) {
            ldsm_x4(qhi[j][0], qhi[j][1], qhi[j][2], qhi[j][3],
                    sb + ar * ROWB + j * 32 + ac);
            ldsm_x4(qlo[j][0], qlo[j][1], qlo[j][2], qlo[j][3],
                    sb + 64 * ROWB + ar * ROWB + j * 32 + ac);
        }
    }
    __syncthreads();

    auto issue_tile = [&](int kt, int st) {
        const size_t goff = (size_t)kt * 64 * 64;
        const uint32_t s0 = sb + st * ATT_STAGE;
        #pragma unroll
        for (int i = 0; i < 4; i++) {
            int idx = i * 128 + tid;           // 0..511
            int row = idx >> 3, ch = idx & 7;
            cp_async16(s0 + row * ROWB + ch * 16, Kg + goff + row * 64 + ch * 8);
            cp_async16(s0 + ATT_ARR + row * ROWB + ch * 16,
                       Vg + goff + row * 64 + ch * 8);
        }
        asm volatile("cp.async.commit_group;" ::: "memory");
    };

    float O[8][4];
    #pragma unroll
    for (int f = 0; f < 8; f++)
        #pragma unroll
        for (int j = 0; j < 4; j++)
            O[f][j] = 0.f;
    float Ol[4] = { 0.f, 0.f, 0.f, 0.f };
    float m0v = -1e30f, m1v = -1e30f;

    issue_tile(0, 0);
    if (ntiles > 1) issue_tile(1, 1);

    const uint32_t b_lrow = (lane & 7) | ((lane >> 1) & 8);
    const uint32_t b_lk   = ((lane >> 3) & 1) * 16;
    const uint32_t v_row  = lane & 15;
    const uint32_t v_cb   = (lane >> 4) * 16;
    const int q0 = qb + wid * 16 + (lane >> 2);
    const int q1 = q0 + 8;

    for (int kt = 0; kt < ntiles; kt++) {
        if (kt + 1 < ntiles)
            asm volatile("cp.async.wait_group 1;" ::: "memory");
        else
            asm volatile("cp.async.wait_group 0;" ::: "memory");
        __syncthreads();
        if (kt + 2 < ntiles) issue_tile(kt + 2, (kt + 2) % 3);

        const uint32_t sK = sb + (kt % 3) * ATT_STAGE;
        const uint32_t sV = sK + ATT_ARR;

        float c[8][4];
        #pragma unroll
        for (int f = 0; f < 8; f++)
            #pragma unroll
            for (int j = 0; j < 4; j++)
                c[f][j] = 0.f;

        #pragma unroll
        for (int j = 0; j < 4; j++) {
            #pragma unroll
            for (int nb = 0; nb < 4; nb++) {
                uint32_t b0, b1, b2, b3;
                ldsm_x4(b0, b1, b2, b3,
                        sK + (nb * 16 + b_lrow) * ROWB + j * 32 + b_lk);
                mma_f16(c[2 * nb],     qhi[j], b0, b1);
                mma_f16(c[2 * nb + 1], qhi[j], b2, b3);
                mma_f16(c[2 * nb],     qlo[j], b0, b1);
                mma_f16(c[2 * nb + 1], qlo[j], b2, b3);
            }
        }

        if (kt == qt) {
            const int kb = kt * 64;
            #pragma unroll
            for (int f = 0; f < 8; f++) {
                const int kc = kb + f * 8 + (lane & 3) * 2;
                if (kc     > q0) c[f][0] = -1e30f;
                if (kc + 1 > q0) c[f][1] = -1e30f;
                if (kc     > q1) c[f][2] = -1e30f;
                if (kc + 1 > q1) c[f][3] = -1e30f;
            }
        }

        float tm0 = -1e30f, tm1 = -1e30f;
        #pragma unroll
        for (int f = 0; f < 8; f++) {
            tm0 = fmaxf(tm0, fmaxf(c[f][0], c[f][1]));
            tm1 = fmaxf(tm1, fmaxf(c[f][2], c[f][3]));
        }
        tm0 = fmaxf(tm0, __shfl_xor_sync(0xffffffffu, tm0, 1));
        tm0 = fmaxf(tm0, __shfl_xor_sync(0xffffffffu, tm0, 2));
        tm1 = fmaxf(tm1, __shfl_xor_sync(0xffffffffu, tm1, 1));
        tm1 = fmaxf(tm1, __shfl_xor_sync(0xffffffffu, tm1, 2));
        const float mn0 = fmaxf(m0v, tm0), mn1 = fmaxf(m1v, tm1);
        const float cor0 = ex2_f32(m0v - mn0), cor1 = ex2_f32(m1v - mn1);
        m0v = mn0; m1v = mn1;

        #pragma unroll
        for (int f = 0; f < 8; f++) {
            O[f][0] *= cor0; O[f][1] *= cor0;
            O[f][2] *= cor1; O[f][3] *= cor1;
        }
        Ol[0] *= cor0; Ol[1] *= cor0;
        Ol[2] *= cor1; Ol[3] *= cor1;

        uint32_t ph[4][4];
        #pragma unroll
        for (int j = 0; j < 4; j++) {
            ph[j][0] = ex2_f16x2(c[2 * j][0]     - mn0, c[2 * j][1]     - mn0);
            ph[j][1] = ex2_f16x2(c[2 * j][2]     - mn1, c[2 * j][3]     - mn1);
            ph[j][2] = ex2_f16x2(c[2 * j + 1][0] - mn0, c[2 * j + 1][1] - mn0);
            ph[j][3] = ex2_f16x2(c[2 * j + 1][2] - mn1, c[2 * j + 1][3] - mn1);
        }

        #pragma unroll
        for (int j = 0; j < 4; j++) {
            mma_f16(Ol, ph[j], ONES2, ONES2);
            #pragma unroll
            for (int db = 0; db < 4; db++) {
                uint32_t b0, b1, b2, b3;
                ldsm_x4t(b0, b1, b2, b3,
                         sV + (j * 16 + v_row) * ROWB + db * 32 + v_cb);
                mma_f16(O[2 * db],     ph[j], b0, b1);
                mma_f16(O[2 * db + 1], ph[j], b2, b3);
            }
        }
    }

    const float inv0 = 1.f / Ol[0], inv1 = 1.f / Ol[2];
    const int b = bh >> 4, h = bh & 15;
    const int t0 = qb + wid * 16 + (lane >> 2);
    const size_t r0 = ((size_t)b * T_ + t0) * C_ + h * 64;
    const size_t r1 = r0 + (size_t)8 * C_;
    #pragma unroll
    for (int f = 0; f < 8; f++) {
        const int d = f * 8 + (lane & 3) * 2;
        uint32_t hi, lo;
        split_pack(O[f][0] * inv0, O[f][1] * inv0, hi, lo);
        *(uint32_t*)(g_Ahi + r0 + d) = hi;
        *(uint32_t*)(g_Alo + r0 + d) = lo;
        split_pack(O[f][2] * inv1, O[f][3] * inv1, hi, lo);
        *(uint32_t*)(g_Ahi + r1 + d) = hi;
        *(uint32_t*)(g_Alo + r1 + d) = lo;
    }
}

// ---------------------------------------------------------------------------
extern "C" void kernel_launch(void* const* d_in, const int* in_sizes, int n_in,
                              void* d_out, int out_size)
{
    const float* x      = (const float*)d_in[0];
    const float* W_qkv  = (const float*)d_in[1];
    const float* b_qkv  = (const float*)d_in[2];
    const float* W_proj = (const float*)d_in[3];
    const float* b_proj = (const float*)d_in[4];
    float* out = (float*)d_out;

    static int inited = 0;
    if (!inited) {
        cudaFuncSetAttribute(gemm_f16_kernel<0>,
                             cudaFuncAttributeMaxDynamicSharedMemorySize, GEMM_SMEM);
        cudaFuncSetAttribute(gemm_f16_kernel<1>,
                             cudaFuncAttributeMaxDynamicSharedMemorySize, GEMM_SMEM);
        cudaFuncSetAttribute(attn_mma_kernel,
                             cudaFuncAttributeMaxDynamicSharedMemorySize, ATT_SMEM);
        inited = 1;
    }

    __half* Wh_d;
    cudaGetSymbolAddress((void**)&Wh_d, g_Wh);

    dim3 tb(32, 8);
    split_w_kernel<<<dim3(128, C_ / 32), tb>>>(W_qkv, W_proj);
    split_act_kernel<<<(M_ * C_) / (256 * 4), 256>>>(x);

    // qkv: 32 x 64 = 2048 CTAs (tiles with n0 >= 1024 skip the A-lo pass)
    gemm_f16_kernel<0><<<dim3(N_QKV / GN, M_ / GM), 128, GEMM_SMEM>>>(
        Wh_d, b_qkv, nullptr, N_QKV);

    attn_mma_kernel<<<dim3(T_ / 64, B_ * H_), 128, ATT_SMEM>>>();

    // proj: 11 x 64 = 704 CTAs, ragged tile guarded, always 2-term.
    gemm_f16_kernel<1><<<dim3((C_ + GN - 1) / GN, M_ / GM), 128, GEMM_SMEM>>>(
        Wh_d + (size_t)N_QKV * C_, b_proj, out, C_);
}

// round 16
// speedup vs baseline: 1.2868x; 1.0952x over previous
#include <cuda_runtime.h>
#include <cuda_fp16.h>
#include <cstdint>

// CausalSelfAttention: B=4, T=2048, C=1024, H=16, dk=64.
// R16: attention output stored as SINGLE fp16 (its lo-term is below proj's
// existing W fp16 rounding), proj GEMM runs 1-term -> half the proj MMAs.
// Everything else identical to R15 (validated).

#define B_   4
#define T_   2048
#define C_   1024
#define H_   16
#define DK_  64
#define M_   (B_ * T_)        // 8192
#define N_QKV (3 * C_)        // 3072

#define QKV_ELEMS ((size_t)B_ * H_ * T_ * DK_)
__device__ __align__(16) __half g_Qhi[QKV_ELEMS];   // scaled by 0.125*log2e
__device__ __align__(16) __half g_Qlo[QKV_ELEMS];
__device__ __align__(16) __half g_K[QKV_ELEMS];     // single fp16
__device__ __align__(16) __half g_V[QKV_ELEMS];     // single fp16
__device__ __align__(16) __half g_Ahi[(size_t)M_ * C_];
__device__ __align__(16) __half g_Alo[(size_t)M_ * C_];  // x-split only
__device__ __align__(16) __half g_Wh[(size_t)(N_QKV + C_ + 128) * C_];

// ---------------------------------------------------------------------------
// helpers
// ---------------------------------------------------------------------------
__device__ __forceinline__ uint32_t smem_u32(const void* p) {
    uint32_t a;
    asm("{ .reg .u64 t; cvta.to.shared.u64 t, %1; cvt.u32.u64 %0, t; }"
        : "=r"(a) : "l"(p));
    return a;
}
__device__ __forceinline__ void cp_async16(uint32_t dst, const void* src) {
    asm volatile("cp.async.ca.shared.global [%0], [%1], 16;"
                 :: "r"(dst), "l"(__cvta_generic_to_global(src)) : "memory");
}
__device__ __forceinline__ void ldsm_x4(uint32_t& r0, uint32_t& r1,
                                        uint32_t& r2, uint32_t& r3, uint32_t a) {
    asm volatile("ldmatrix.sync.aligned.m8n8.x4.shared.b16 {%0,%1,%2,%3}, [%4];"
                 : "=r"(r0), "=r"(r1), "=r"(r2), "=r"(r3) : "r"(a));
}
__device__ __forceinline__ void ldsm_x4t(uint32_t& r0, uint32_t& r1,
                                         uint32_t& r2, uint32_t& r3, uint32_t a) {
    asm volatile("ldmatrix.sync.aligned.m8n8.x4.trans.shared.b16 {%0,%1,%2,%3}, [%4];"
                 : "=r"(r0), "=r"(r1), "=r"(r2), "=r"(r3) : "r"(a));
}
__device__ __forceinline__ void mma_f16(float* c, const uint32_t* a,
                                        uint32_t b0, uint32_t b1) {
    asm volatile(
        "mma.sync.aligned.m16n8k16.row.col.f32.f16.f16.f32 "
        "{%0,%1,%2,%3}, {%4,%5,%6,%7}, {%8,%9}, {%0,%1,%2,%3};"
        : "+f"(c[0]), "+f"(c[1]), "+f"(c[2]), "+f"(c[3])
        : "r"(a[0]), "r"(a[1]), "r"(a[2]), "r"(a[3]), "r"(b0), "r"(b1));
}
__device__ __forceinline__ void split_pack(float x, float y,
                                           uint32_t& hi, uint32_t& lo) {
    __half hx = __float2half_rn(x);
    __half hy = __float2half_rn(y);
    __half2 h; h.x = hx; h.y = hy;
    hi = *(uint32_t*)&h;
    __half2 l;
    l.x = __float2half_rn(x - __half2float(hx));
    l.y = __float2half_rn(y - __half2float(hy));
    lo = *(uint32_t*)&l;
}
__device__ __forceinline__ uint32_t pack_h2(float x, float y) {
    __half2 h; h.x = __float2half_rn(x); h.y = __float2half_rn(y);
    return *(uint32_t*)&h;
}
__device__ __forceinline__ uint32_t ex2_f16x2(float x, float y) {
    uint32_t d;
    asm("{ .reg .b32 t;\n\t"
        "cvt.rn.f16x2.f32 t, %2, %1;\n\t"
        "ex2.approx.f16x2 %0, t; }"
        : "=r"(d) : "f"(x), "f"(y));
    return d;
}
__device__ __forceinline__ float ex2_f32(float x) {
    float d;
    asm("ex2.approx.f32 %0, %1;" : "=f"(d) : "f"(x));
    return d;
}

// ---------------------------------------------------------------------------
// Split fp32 -> fp16 hi/lo (x input only).
// ---------------------------------------------------------------------------
__global__ void __launch_bounds__(256) split_act_kernel(const float* __restrict__ src)
{
    size_t i = ((size_t)blockIdx.x * 256 + threadIdx.x) * 4;
    float4 v = *(const float4*)(src + i);
    __half hx = __float2half_rn(v.x);
    __half hy = __float2half_rn(v.y);
    __half hz = __float2half_rn(v.z);
    __half hw = __float2half_rn(v.w);
    __half h2[4] = { hx, hy, hz, hw };
    *(uint2*)(g_Ahi + i) = *(uint2*)h2;
    __half l2[4] = {
        __float2half_rn(v.x - __half2float(hx)),
        __float2half_rn(v.y - __half2float(hy)),
        __float2half_rn(v.z - __half2float(hz)),
        __float2half_rn(v.w - __half2float(hw)) };
    *(uint2*)(g_Alo + i) = *(uint2*)l2;
}

// ---------------------------------------------------------------------------
// Merged weight transpose: bx < 96 -> W_qkv, else W_proj (offset N_QKV).
// ---------------------------------------------------------------------------
__global__ void __launch_bounds__(256) split_w_kernel(
    const float* __restrict__ Wq, const float* __restrict__ Wp)
{
    __shared__ float tile[32][33];
    const int tx = threadIdx.x, ty = threadIdx.y;
    const int bx = blockIdx.x;
    const bool is_q = bx < (N_QKV / 32);
    const float* W = is_q ? Wq : Wp;
    const int Ncols = is_q ? N_QKV : C_;
    const int row_off = is_q ? 0 : N_QKV;
    const int n0 = (is_q ? bx : bx - N_QKV / 32) * 32;
    const int k0 = blockIdx.y * 32;
    #pragma unroll
    for (int j = ty; j < 32; j += 8)
        tile[j][tx] = W[(size_t)(k0 + j) * Ncols + n0 + tx];
    __syncthreads();
    #pragma unroll
    for (int j = ty; j < 32; j += 8) {
        size_t o = (size_t)(row_off + n0 + j) * C_ + k0 + tx;
        g_Wh[o] = __float2half_rn(tile[tx][j]);
    }
}

// ---------------------------------------------------------------------------
// mma.sync fp16 GEMM. Tile 128x96x32, 4 warps (2m x 2n), warp tile 64x48.
// 2-stage ring, one barrier per chunk, 3 CTAs/SM.
// MODE 0 (qkv): Q/K/V scatter epilogue; A-lo pass only for Q tiles (n0 < C_).
// MODE 1 (proj): fp32 out (+Nlim guard); single-term (A stored fp16 only).
// ---------------------------------------------------------------------------
#define GM 128
#define GN 96
#define KC 32
#define NCHUNK (C_ / KC)
#define A_ST (GM * 80)              // 10240
#define B_ST (GN * 80)              // 7680
#define STAGE (2 * A_ST + B_ST)     // 28160
#define GEMM_SMEM (2 * STAGE)       // 56320

#define QSCALE 0.18033688011112042f  // 0.125 * log2(e)

extern __shared__ char gemm_smem[];

template<int MODE>
__global__ void __launch_bounds__(128, 3) gemm_f16_kernel(
    const __half* __restrict__ gB,
    const float* __restrict__ bias,
    float* __restrict__ Cout,
    int Nlim)
{
    const int tid = threadIdx.x;
    const int lane = tid & 31;
    const int wid = tid >> 5;
    const int wm = wid & 1;
    const int wn = wid >> 1;
    const int m0 = blockIdx.y * GM;
    const int n0 = blockIdx.x * GN;

    // A-lo pass: only for qkv tiles that produce Q columns.
    const bool do_lo = (MODE == 0) && (n0 < C_);

    const uint32_t sbase = smem_u32(gemm_smem);

    float c[4][6][4];
    #pragma unroll
    for (int i = 0; i < 4; i++)
        #pragma unroll
        for (int j = 0; j < 6; j++)
            #pragma unroll
            for (int k = 0; k < 4; k++)
                c[i][j][k] = 0.f;

    auto issue = [&](int ch) {
        const int k0 = ch * KC;
        const uint32_t sb = sbase + (ch & 1) * STAGE;
        #pragma unroll
        for (int i = 0; i < 4; i++) {          // A hi (+ lo when needed)
            int idx = i * 128 + tid;
            int row = idx >> 2, cc = idx & 3;
            size_t go = ((size_t)(m0 + row) << 10) + k0 + cc * 8;
            uint32_t dof = row * 80 + cc * 16;
            cp_async16(sb + dof, g_Ahi + go);
            if (do_lo)
                cp_async16(sb + A_ST + dof, g_Alo + go);
        }
        #pragma unroll
        for (int i = 0; i < 3; i++) {          // B single fp16
            int idx = i * 128 + tid;
            int row = idx >> 2, cc = idx & 3;
            size_t go = ((size_t)(n0 + row) << 10) + k0 + cc * 8;
            uint32_t dof = row * 80 + cc * 16;
            cp_async16(sb + 2 * A_ST + dof, gB + go);
        }
        asm volatile("cp.async.commit_group;" ::: "memory");
    };

    issue(0);

    const uint32_t a_lrow = (lane & 15);
    const uint32_t a_lk   = (lane >> 4) * 16;
    const uint32_t b_lrow = (lane & 7) | ((lane >> 1) & 8);
    const uint32_t b_lk   = ((lane >> 3) & 1) * 16;

    for (int ch = 0; ch < NCHUNK; ch++) {
        asm volatile("cp.async.wait_group 0;" ::: "memory");
        __syncthreads();
        if (ch + 1 < NCHUNK) issue(ch + 1);

        const uint32_t sA = sbase + (ch & 1) * STAGE;
        const uint32_t sB = sA + 2 * A_ST;

        #pragma unroll
        for (int ks = 0; ks < 2; ks++) {
            const uint32_t kb = ks * 32;
            uint32_t ahi[4][4], bb[3][4];
            #pragma unroll
            for (int mf = 0; mf < 4; mf++) {
                uint32_t ad = sA + (wm * 64 + mf * 16 + a_lrow) * 80 + kb + a_lk;
                ldsm_x4(ahi[mf][0], ahi[mf][1], ahi[mf][2], ahi[mf][3], ad);
            }
            #pragma unroll
            for (int np = 0; np < 3; np++) {
                uint32_t bd = sB + (wn * 48 + np * 16 + b_lrow) * 80 + kb + b_lk;
                ldsm_x4(bb[np][0], bb[np][1], bb[np][2], bb[np][3], bd);
            }
            #pragma unroll
            for (int mf = 0; mf < 4; mf++)
                #pragma unroll
                for (int np = 0; np < 3; np++) {
                    mma_f16(c[mf][2 * np],     ahi[mf], bb[np][0], bb[np][1]);
                    mma_f16(c[mf][2 * np + 1], ahi[mf], bb[np][2], bb[np][3]);
                }
            if (do_lo) {
                #pragma unroll
                for (int mf = 0; mf < 4; mf++) {
                    uint32_t alo[4];
                    uint32_t ad = sA + A_ST + (wm * 64 + mf * 16 + a_lrow) * 80 + kb + a_lk;
                    ldsm_x4(alo[0], alo[1], alo[2], alo[3], ad);
                    #pragma unroll
                    for (int np = 0; np < 3; np++) {
                        mma_f16(c[mf][2 * np],     alo, bb[np][0], bb[np][1]);
                        mma_f16(c[mf][2 * np + 1], alo, bb[np][2], bb[np][3]);
                    }
                }
            }
        }
    }

    // ---- epilogue ----
    #pragma unroll
    for (int mf = 0; mf < 4; mf++) {
        const int mrow = m0 + wm * 64 + mf * 16 + (lane >> 2);
        #pragma unroll
        for (int nf = 0; nf < 6; nf++) {
            const int n = n0 + wn * 48 + nf * 8 + (lane & 3) * 2;
            if (MODE == 0) {
                const float bx = bias[n], by = bias[n + 1];
                const int which = n >> 10;                 // 0=Q,1=K,2=V
                const int h = (n >> 6) & 15;
                const int d = n & 63;
                const int b = mrow >> 11, t = mrow & (T_ - 1);
                size_t base = (((size_t)(b * H_ + h) * T_ + t) << 6) + d;
                float v0 = c[mf][nf][0] + bx, v1 = c[mf][nf][1] + by;
                float v2 = c[mf][nf][2] + bx, v3 = c[mf][nf][3] + by;
                if (which == 0) {
                    uint32_t hi, lo;
                    split_pack(v0 * QSCALE, v1 * QSCALE, hi, lo);
                    *(uint32_t*)(g_Qhi + base) = hi;
                    *(uint32_t*)(g_Qlo + base) = lo;
                    split_pack(v2 * QSCALE, v3 * QSCALE, hi, lo);
                    *(uint32_t*)(g_Qhi + base + 512) = hi;   // (t+8) << 6
                    *(uint32_t*)(g_Qlo + base + 512) = lo;
                } else {
                    __half* dst = (which == 1) ? g_K : g_V;
                    *(uint32_t*)(dst + base)       = pack_h2(v0, v1);
                    *(uint32_t*)(dst + base + 512) = pack_h2(v2, v3);
                }
            } else if (n < Nlim) {
                const float bx = bias[n], by = bias[n + 1];
                float* p = Cout + (size_t)mrow * C_ + n;
                p[0] = c[mf][nf][0] + bx;
                p[1] = c[mf][nf][1] + by;
                p += (size_t)8 * C_;
                p[0] = c[mf][nf][2] + bx;
                p[1] = c[mf][nf][3] + by;
            }
        }
    }
}

// ---------------------------------------------------------------------------
// MMA flash attention (fp16), log2-domain softmax, ex2.f16x2 P, ones-MMA l.
// 64 q-rows per CTA, 128 threads (4 warps), 3 CTAs/SM, 3-stage K/V ring.
// R16: epilogue writes SINGLE fp16 (g_Ahi only) — proj consumes 1-term.
// ---------------------------------------------------------------------------
#define ROWB 144
#define ATT_ARR (64 * ROWB)          // 9216
#define ATT_STAGE (2 * ATT_ARR)      // 18432 (K + V)
#define ATT_SMEM (3 * ATT_STAGE)     // 55296
#define ONES2 0x3C003C00u            // fp16x2 {1.0, 1.0}

extern __shared__ char att_smem[];

__global__ void __launch_bounds__(128, 3) attn_mma_kernel()
{
    const uint32_t sb = smem_u32(att_smem);
    const int tid = threadIdx.x, lane = tid & 31, wid = tid >> 5;   // 4 warps
    const int bh = blockIdx.y;
    const int qt = (int)(gridDim.x - 1) - (int)blockIdx.x;   // heavy-first
    const int qb = qt * 64;
    const int ntiles = qt + 1;

    const size_t bhoff = (size_t)bh * T_ * DK_;
    const __half* Kg = g_K + bhoff;
    const __half* Vg = g_V + bhoff;

    {
        const __half* Qh = g_Qhi + bhoff + (size_t)qb * DK_;
        const __half* Ql = g_Qlo + bhoff + (size_t)qb * DK_;
        #pragma unroll
        for (int i = 0; i < 4; i++) {
            int idx = i * 128 + tid;          // 0..511
            int row = idx >> 3, ch = idx & 7;
            cp_async16(sb + row * ROWB + ch * 16, Qh + row * 64 + ch * 8);
            cp_async16(sb + 64 * ROWB + row * ROWB + ch * 16, Ql + row * 64 + ch * 8);
        }
        asm volatile("cp.async.commit_group;" ::: "memory");
        asm volatile("cp.async.wait_group 0;" ::: "memory");
        __syncthreads();
    }
    uint32_t qhi[4][4], qlo[4][4];
    {
        const uint32_t ar = wid * 16 + (lane & 15);          // 0..63
        const uint32_t ac = (lane >> 4) * 16;
        #pragma unroll
        for (int j = 0; j < 4; j++) {
            ldsm_x4(qhi[j][0], qhi[j][1], qhi[j][2], qhi[j][3],
                    sb + ar * ROWB + j * 32 + ac);
            ldsm_x4(qlo[j][0], qlo[j][1], qlo[j][2], qlo[j][3],
                    sb + 64 * ROWB + ar * ROWB + j * 32 + ac);
        }
    }
    __syncthreads();

    auto issue_tile = [&](int kt, int st) {
        const size_t goff = (size_t)kt * 64 * 64;
        const uint32_t s0 = sb + st * ATT_STAGE;
        #pragma unroll
        for (int i = 0; i < 4; i++) {
            int idx = i * 128 + tid;           // 0..511
            int row = idx >> 3, ch = idx & 7;
            cp_async16(s0 + row * ROWB + ch * 16, Kg + goff + row * 64 + ch * 8);
            cp_async16(s0 + ATT_ARR + row * ROWB + ch * 16,
                       Vg + goff + row * 64 + ch * 8);
        }
        asm volatile("cp.async.commit_group;" ::: "memory");
    };

    float O[8][4];
    #pragma unroll
    for (int f = 0; f < 8; f++)
        #pragma unroll
        for (int j = 0; j < 4; j++)
            O[f][j] = 0.f;
    float Ol[4] = { 0.f, 0.f, 0.f, 0.f };
    float m0v = -1e30f, m1v = -1e30f;

    issue_tile(0, 0);
    if (ntiles > 1) issue_tile(1, 1);

    const uint32_t b_lrow = (lane & 7) | ((lane >> 1) & 8);
    const uint32_t b_lk   = ((lane >> 3) & 1) * 16;
    const uint32_t v_row  = lane & 15;
    const uint32_t v_cb   = (lane >> 4) * 16;
    const int q0 = qb + wid * 16 + (lane >> 2);
    const int q1 = q0 + 8;

    for (int kt = 0; kt < ntiles; kt++) {
        if (kt + 1 < ntiles)
            asm volatile("cp.async.wait_group 1;" ::: "memory");
        else
            asm volatile("cp.async.wait_group 0;" ::: "memory");
        __syncthreads();
        if (kt + 2 < ntiles) issue_tile(kt + 2, (kt + 2) % 3);

        const uint32_t sK = sb + (kt % 3) * ATT_STAGE;
        const uint32_t sV = sK + ATT_ARR;

        float c[8][4];
        #pragma unroll
        for (int f = 0; f < 8; f++)
            #pragma unroll
            for (int j = 0; j < 4; j++)
                c[f][j] = 0.f;

        #pragma unroll
        for (int j = 0; j < 4; j++) {
            #pragma unroll
            for (int nb = 0; nb < 4; nb++) {
                uint32_t b0, b1, b2, b3;
                ldsm_x4(b0, b1, b2, b3,
                        sK + (nb * 16 + b_lrow) * ROWB + j * 32 + b_lk);
                mma_f16(c[2 * nb],     qhi[j], b0, b1);
                mma_f16(c[2 * nb + 1], qhi[j], b2, b3);
                mma_f16(c[2 * nb],     qlo[j], b0, b1);
                mma_f16(c[2 * nb + 1], qlo[j], b2, b3);
            }
        }

        if (kt == qt) {
            const int kb = kt * 64;
            #pragma unroll
            for (int f = 0; f < 8; f++) {
                const int kc = kb + f * 8 + (lane & 3) * 2;
                if (kc     > q0) c[f][0] = -1e30f;
                if (kc + 1 > q0) c[f][1] = -1e30f;
                if (kc     > q1) c[f][2] = -1e30f;
                if (kc + 1 > q1) c[f][3] = -1e30f;
            }
        }

        float tm0 = -1e30f, tm1 = -1e30f;
        #pragma unroll
        for (int f = 0; f < 8; f++) {
            tm0 = fmaxf(tm0, fmaxf(c[f][0], c[f][1]));
            tm1 = fmaxf(tm1, fmaxf(c[f][2], c[f][3]));
        }
        tm0 = fmaxf(tm0, __shfl_xor_sync(0xffffffffu, tm0, 1));
        tm0 = fmaxf(tm0, __shfl_xor_sync(0xffffffffu, tm0, 2));
        tm1 = fmaxf(tm1, __shfl_xor_sync(0xffffffffu, tm1, 1));
        tm1 = fmaxf(tm1, __shfl_xor_sync(0xffffffffu, tm1, 2));
        const float mn0 = fmaxf(m0v, tm0), mn1 = fmaxf(m1v, tm1);
        const float cor0 = ex2_f32(m0v - mn0), cor1 = ex2_f32(m1v - mn1);
        m0v = mn0; m1v = mn1;

        #pragma unroll
        for (int f = 0; f < 8; f++) {
            O[f][0] *= cor0; O[f][1] *= cor0;
            O[f][2] *= cor1; O[f][3] *= cor1;
        }
        Ol[0] *= cor0; Ol[1] *= cor0;
        Ol[2] *= cor1; Ol[3] *= cor1;

        uint32_t ph[4][4];
        #pragma unroll
        for (int j = 0; j < 4; j++) {
            ph[j][0] = ex2_f16x2(c[2 * j][0]     - mn0, c[2 * j][1]     - mn0);
            ph[j][1] = ex2_f16x2(c[2 * j][2]     - mn1, c[2 * j][3]     - mn1);
            ph[j][2] = ex2_f16x2(c[2 * j + 1][0] - mn0, c[2 * j + 1][1] - mn0);
            ph[j][3] = ex2_f16x2(c[2 * j + 1][2] - mn1, c[2 * j + 1][3] - mn1);
        }

        #pragma unroll
        for (int j = 0; j < 4; j++) {
            mma_f16(Ol, ph[j], ONES2, ONES2);
            #pragma unroll
            for (int db = 0; db < 4; db++) {
                uint32_t b0, b1, b2, b3;
                ldsm_x4t(b0, b1, b2, b3,
                         sV + (j * 16 + v_row) * ROWB + db * 32 + v_cb);
                mma_f16(O[2 * db],     ph[j], b0, b1);
                mma_f16(O[2 * db + 1], ph[j], b2, b3);
            }
        }
    }

    // epilogue: normalize, single fp16 pack, write [b*T+t][h*64+d]
    const float inv0 = 1.f / Ol[0], inv1 = 1.f / Ol[2];
    const int b = bh >> 4, h = bh & 15;
    const int t0 = qb + wid * 16 + (lane >> 2);
    const size_t r0 = ((size_t)b * T_ + t0) * C_ + h * 64;
    const size_t r1 = r0 + (size_t)8 * C_;
    #pragma unroll
    for (int f = 0; f < 8; f++) {
        const int d = f * 8 + (lane & 3) * 2;
        *(uint32_t*)(g_Ahi + r0 + d) = pack_h2(O[f][0] * inv0, O[f][1] * inv0);
        *(uint32_t*)(g_Ahi + r1 + d) = pack_h2(O[f][2] * inv1, O[f][3] * inv1);
    }
}

// ---------------------------------------------------------------------------
extern "C" void kernel_launch(void* const* d_in, const int* in_sizes, int n_in,
                              void* d_out, int out_size)
{
    const float* x      = (const float*)d_in[0];
    const float* W_qkv  = (const float*)d_in[1];
    const float* b_qkv  = (const float*)d_in[2];
    const float* W_proj = (const float*)d_in[3];
    const float* b_proj = (const float*)d_in[4];
    float* out = (float*)d_out;

    static int inited = 0;
    if (!inited) {
        cudaFuncSetAttribute(gemm_f16_kernel<0>,
                             cudaFuncAttributeMaxDynamicSharedMemorySize, GEMM_SMEM);
        cudaFuncSetAttribute(gemm_f16_kernel<1>,
                             cudaFuncAttributeMaxDynamicSharedMemorySize, GEMM_SMEM);
        cudaFuncSetAttribute(attn_mma_kernel,
                             cudaFuncAttributeMaxDynamicSharedMemorySize, ATT_SMEM);
        inited = 1;
    }

    __half* Wh_d;
    cudaGetSymbolAddress((void**)&Wh_d, g_Wh);

    dim3 tb(32, 8);
    split_w_kernel<<<dim3(128, C_ / 32), tb>>>(W_qkv, W_proj);
    split_act_kernel<<<(M_ * C_) / (256 * 4), 256>>>(x);

    // qkv: 32 x 64 = 2048 CTAs (K/V tiles skip the A-lo pass)
    gemm_f16_kernel<0><<<dim3(N_QKV / GN, M_ / GM), 128, GEMM_SMEM>>>(
        Wh_d, b_qkv, nullptr, N_QKV);

    attn_mma_kernel<<<dim3(T_ / 64, B_ * H_), 128, ATT_SMEM>>>();

    // proj: 11 x 64 = 704 CTAs, single-term A, ragged tile guarded.
    gemm_f16_kernel<1><<<dim3((C_ + GN - 1) / GN, M_ / GM), 128, GEMM_SMEM>>>(
        Wh_d + (size_t)N_QKV * C_, b_proj, out, C_);
}